// round 10
// baseline (speedup 1.0000x reference)
#include <cuda_runtime.h>
#include <cuda_bf16.h>
#include <cstdint>
#include <cstddef>

#define H    300
#define B    256
#define NX   128
#define NY   128
#define VY   32000
#define NROWS 32512          /* 127*256 decoder logit rows */
#define KP   312             /* padded K stride in bf16 halves for GEMM */

// ---- clustered recurrence geometry ----
#define GJ   320             /* padded j stride of transposed W in gmem */
#define GK2  304             /* padded k dimension */
#define JH   152             /* j-rows held per CTA (GK2/2) */
#define BSLC 4               /* batch columns per cluster */
#define RTHREADS 608         /* JH * 4 k-quarters */
// smem: W half + 2x h + partials + bias
#define OFF_W    0
#define OFF_H    (GK2*JH*4)                    /* 184832 */
#define OFF_RED  (OFF_H + 2*GK2*BSLC*4)        /* +9728  */
#define OFF_BIAS (OFF_RED + 4*JH*BSLC*4)       /* +9728  */
#define CSMEM    (OFF_BIAS + JH*4)             /* 204896 */

// ------------------------- scratch (device globals) -------------------------
__device__ __align__(16) __nv_bfloat16  g_hB[(size_t)NROWS*KP];   // decoder hidden rows (bf16)
__device__ __align__(16) __nv_bfloat16  g_wB[(size_t)VY*KP];      // outW in bf16, padded
__device__ __align__(16) float g_WtE[GK2*GJ];                     // encW transposed+padded
__device__ __align__(16) float g_WtD[GK2*GJ];                     // decW transposed+padded
__device__ float g_lse[NROWS];
__device__ float g_tl[NROWS];

// ------------------------- PTX helpers -------------------------
__device__ __forceinline__ uint32_t sptr(const void* p) {
    return (uint32_t)__cvta_generic_to_shared(p);
}
__device__ __forceinline__ void mbar_init(uint32_t mbar, uint32_t cnt) {
    asm volatile("mbarrier.init.shared.b64 [%0], %1;" :: "r"(mbar), "r"(cnt) : "memory");
}
__device__ __forceinline__ void mbar_expect_tx(uint32_t mbar, uint32_t bytes) {
    asm volatile("mbarrier.arrive.expect_tx.shared.b64 _, [%0], %1;" :: "r"(mbar), "r"(bytes) : "memory");
}
__device__ __forceinline__ void mbar_wait(uint32_t mbar, uint32_t phase) {
    uint32_t done;
    do {
        asm volatile("{\n\t.reg .pred p;\n\t"
                     "mbarrier.try_wait.parity.shared::cta.b64 p, [%1], %2;\n\t"
                     "selp.b32 %0, 1, 0, p;\n\t}"
                     : "=r"(done) : "r"(mbar), "r"(phase) : "memory");
    } while (!done);
}
__device__ __forceinline__ void bulk_g2s(uint32_t dst, const void* src, uint32_t bytes, uint32_t mbar) {
    asm volatile("cp.async.bulk.shared::cluster.global.mbarrier::complete_tx::bytes [%0], [%1], %2, [%3];"
                 :: "r"(dst), "l"(src), "r"(bytes), "r"(mbar) : "memory");
}
__device__ __forceinline__ void ldmx4(uint32_t* r, uint32_t addr) {
    asm volatile("ldmatrix.sync.aligned.m8n8.x4.shared.b16 {%0,%1,%2,%3}, [%4];"
                 : "=r"(r[0]), "=r"(r[1]), "=r"(r[2]), "=r"(r[3]) : "r"(addr));
}
__device__ __forceinline__ void mma_bf16(float* c, const uint32_t* a, uint32_t b0, uint32_t b1) {
    asm volatile("mma.sync.aligned.m16n8k16.row.col.f32.bf16.bf16.f32 "
                 "{%0,%1,%2,%3},{%4,%5,%6,%7},{%8,%9},{%0,%1,%2,%3};"
                 : "+f"(c[0]), "+f"(c[1]), "+f"(c[2]), "+f"(c[3])
                 : "r"(a[0]), "r"(a[1]), "r"(a[2]), "r"(a[3]), "r"(b0), "r"(b1));
}
__device__ __forceinline__ uint32_t ctarank() {
    uint32_t r; asm("mov.u32 %0, %%cluster_ctarank;" : "=r"(r)); return r;
}
__device__ __forceinline__ void dsmem_st_f32(uint32_t addr, uint32_t rank, float v) {
    uint32_t pa;
    asm volatile("mapa.shared::cluster.u32 %0, %1, %2;" : "=r"(pa) : "r"(addr), "r"(rank));
    asm volatile("st.shared::cluster.f32 [%0], %1;" :: "r"(pa), "f"(v) : "memory");
}
__device__ __forceinline__ void cluster_sync() {
    asm volatile("barrier.cluster.arrive.aligned;" ::: "memory");
    asm volatile("barrier.cluster.wait.aligned;" ::: "memory");
}

// ------------------------- init: zero pad cols of g_hB -------------------------
__global__ void init_kernel() {
    int stride = gridDim.x * blockDim.x;
    int i0 = blockIdx.x * blockDim.x + threadIdx.x;
    for (int i = i0; i < NROWS*3; i += stride) {
        int r = i / 3, c = i - r*3;
        *(uint32_t*)((char*)g_hB + (size_t)r*(KP*2) + 600 + c*4) = 0u;
    }
}

// ------------------------- outW fp32 -> bf16 padded -------------------------
__global__ void wconv_kernel(const float* __restrict__ outW) {
    int stride = gridDim.x * blockDim.x;
    for (int i = blockIdx.x * blockDim.x + threadIdx.x; i < VY*KP; i += stride) {
        int v = i / KP, k = i - v*KP;
        g_wB[i] = __float2bfloat16((k < H) ? outW[(size_t)v*H + k] : 0.f);
    }
}

// ------------------------- W -> transposed padded Wt[k][j] -------------------------
__global__ void wtrans_kernel(const float* __restrict__ W, float* __restrict__ Wt) {
    int stride = gridDim.x * blockDim.x;
    for (int i = blockIdx.x * blockDim.x + threadIdx.x; i < GK2*GJ; i += stride) {
        int k = i / GJ, j = i - k*GJ;
        Wt[i] = (j < H && k < H) ? W[j*H + k] : 0.f;
    }
}

// ------------------------- clustered persistent recurrence -------------------------
// 64 clusters of 2 CTAs. Each CTA caches W[k][j-half] (185KB) in smem once per phase.
// Cluster owns 4 batch columns; h (all 304 k) replicated in both CTAs' smem.
// 608 threads: j = tid%152, kq = tid/152 (76 k's each).
__global__ void __launch_bounds__(RTHREADS, 1) __cluster_dims__(2, 1, 1)
rnn_cluster(
    const float* __restrict__ enc_emb, const int* __restrict__ x, const float* __restrict__ encb,
    const float* __restrict__ dec_emb, const int* __restrict__ y, const float* __restrict__ decb)
{
    extern __shared__ __align__(16) char smraw[];
    float* sW    = (float*)(smraw + OFF_W);     // [GK2][JH]
    float* sH    = (float*)(smraw + OFF_H);     // [2][GK2*4] layout h[k*4+b]
    float* sRed  = (float*)(smraw + OFF_RED);   // [4][JH] float4
    float* sBias = (float*)(smraw + OFF_BIAS);  // [JH]

    const int tid = threadIdx.x;
    const uint32_t rank = ctarank();
    const int j  = tid % JH;
    const int kq = tid / JH;
    const int b0 = (blockIdx.x >> 1) * BSLC;

    // zero both h buffers
    for (int i = tid; i < 2*GK2*BSLC; i += RTHREADS) sH[i] = 0.f;
    cluster_sync();

    int p = 0;
    for (int t = 0; t < NX + NY - 1; t++) {
        const bool enc = (t < NX);
        const float* emb = enc ? enc_emb : dec_emb;
        const int*   idx = enc ? (x + t*B) : (y + (t - NX)*B);

        if (t == 0 || t == NX) {   // load W half + bias (once per phase)
            const float* Wt   = enc ? g_WtE : g_WtD;
            const float* bsrc = enc ? encb : decb;
            for (int i = tid; i < GK2*(JH/4); i += RTHREADS) {
                int row = i / (JH/4), q = i - row*(JH/4);
                *(float4*)(sW + row*JH + q*4) =
                    *(const float4*)(Wt + row*GJ + rank*JH + q*4);
            }
            for (int i = tid; i < JH; i += RTHREADS) {
                int jg = rank*JH + i;
                sBias[i] = (jg < H) ? bsrc[jg] : 0.f;
            }
            __syncthreads();
        }

        // ---- partial GEMV over this thread's 76 k's ----
        const float* hcur = sH + p*(GK2*BSLC);
        float ax = 0.f, ay = 0.f, az = 0.f, aw = 0.f;
        const float* wp = sW + (kq*76)*JH + j;
        const float4* hp = (const float4*)(hcur) + kq*76;
        #pragma unroll 4
        for (int i = 0; i < 76; i++) {
            float w = wp[i*JH];
            float4 h = hp[i];
            ax += w*h.x; ay += w*h.y; az += w*h.z; aw += w*h.w;
        }
        ((float4*)sRed)[kq*JH + j] = make_float4(ax, ay, az, aw);
        __syncthreads();

        // ---- finalize: threads 0..151, j-row jg = rank*JH + tid ----
        if (tid < JH) {
            const float4* r4 = (const float4*)sRed;
            float4 s0 = r4[tid], s1 = r4[JH + tid], s2 = r4[2*JH + tid], s3 = r4[3*JH + tid];
            float sv[4] = { s0.x+s1.x+s2.x+s3.x, s0.y+s1.y+s2.y+s3.y,
                            s0.z+s1.z+s2.z+s3.z, s0.w+s1.w+s2.w+s3.w };
            const int jg = rank*JH + tid;
            float* hn = sH + (p ^ 1)*(GK2*BSLC);
            const float bi = sBias[tid];
            #pragma unroll
            for (int b = 0; b < BSLC; b++) {
                float v = 0.f;
                if (jg < H) {
                    int ix = idx[b0 + b];
                    v = fmaxf(sv[b] + emb[(size_t)ix*H + jg] + bi, 0.f);
                }
                hn[jg*BSLC + b] = v;
                dsmem_st_f32(sptr(&hn[jg*BSLC + b]), rank ^ 1u, v);
                if (!enc && jg < H)
                    g_hB[(size_t)((t - NX)*B + b0 + b)*KP + jg] = __float2bfloat16(v);
            }
        }
        cluster_sync();
        p ^= 1;
    }
}

// ------------------------- target logit gather GEMV -------------------------
__global__ void __launch_bounds__(256) tl_kernel(const int* __restrict__ y,
                                                 const float* __restrict__ outb)
{
    int gw = blockIdx.x * 8 + (threadIdx.x >> 5);
    int lane = threadIdx.x & 31;
    if (gw >= NROWS) return;
    int t = gw >> 8, b = gw & 255;
    int tgt = y[(t+1)*B + b];
    const __nv_bfloat162* hr = (const __nv_bfloat162*)(g_hB + (size_t)gw*KP);
    const __nv_bfloat162* wr = (const __nv_bfloat162*)(g_wB + (size_t)tgt*KP);
    float acc = 0.f;
    for (int k = lane; k < KP/2; k += 32) {
        float2 hv = __bfloat1622float2(hr[k]);
        float2 wv = __bfloat1622float2(wr[k]);
        acc += hv.x*wv.x + hv.y*wv.y;
    }
    #pragma unroll
    for (int s = 16; s; s >>= 1) acc += __shfl_xor_sync(0xffffffffu, acc, s);
    if (lane == 0) g_tl[gw] = acc + __ldg(outb + tgt);
}

// ------------------------- fused GEMM + online log-sum-exp -------------------------
#define OFF_A      0
#define OFF_B0     79872
#define OFF_B1     119808
#define OFF_BIAS0  159744
#define OFF_BIAS1  160000
#define OFF_MS     160256
#define OFF_MBAR   162304
#define GSMEM      162368
#define A_BYTES    79872u     /* 128*312*2 */
#define B_BYTES    39936u     /* 64*312*2 */

__global__ void __launch_bounds__(128, 1) gemm_lse_kernel(const float* __restrict__ outb)
{
    extern __shared__ __align__(1024) char smc[];
    __nv_bfloat16* sA = (__nv_bfloat16*)(smc + OFF_A);
    __nv_bfloat16* sB[2] = { (__nv_bfloat16*)(smc + OFF_B0), (__nv_bfloat16*)(smc + OFF_B1) };
    float* sBias[2] = { (float*)(smc + OFF_BIAS0), (float*)(smc + OFF_BIAS1) };
    float* sMS = (float*)(smc + OFF_MS);
    uint64_t* mbar = (uint64_t*)(smc + OFF_MBAR);

    const int tid = threadIdx.x, lane = tid & 31, wid = tid >> 5;
    const int wr = wid >> 1, wc = wid & 1;
    const __nv_bfloat16* gA = g_hB + (size_t)blockIdx.x * 128 * KP;

    if (tid == 0) {
        mbar_init(sptr(&mbar[0]), 1);
        mbar_init(sptr(&mbar[1]), 1);
        mbar_init(sptr(&mbar[2]), 1);
    }
    __syncthreads();
    if (tid == 0) {
        uint32_t mA = sptr(&mbar[0]);
        mbar_expect_tx(mA, A_BYTES);
        bulk_g2s(sptr(sA), gA, A_BYTES, mA);
        uint32_t m0 = sptr(&mbar[1]);
        mbar_expect_tx(m0, B_BYTES + 256);
        bulk_g2s(sptr(sB[0]), g_wB, B_BYTES, m0);
        bulk_g2s(sptr(sBias[0]), outb, 256, m0);
    }

    const uint32_t aBase = sptr(sA) + (uint32_t)(((wr*64 + (lane & 15))*KP + ((lane >> 4) << 3)) * 2);
    const uint32_t bOff  = (uint32_t)(((wc*32 + (lane & 15))*KP + ((lane >> 4) << 3)) * 2);

    float mrow[8], srow[8];
    #pragma unroll
    for (int i = 0; i < 8; i++) { mrow[i] = -1e30f; srow[i] = 0.f; }

    mbar_wait(sptr(&mbar[0]), 0);

    const int colL = wc*32 + ((lane & 3) << 1);
    const int g = lane >> 2;

    for (int t = 0; t < 500; t++) {
        const int buf = t & 1;
        if (tid == 0 && t + 1 < 500) {
            const int nb = buf ^ 1;
            uint32_t mN = sptr(&mbar[1 + nb]);
            mbar_expect_tx(mN, B_BYTES + 256);
            bulk_g2s(sptr(sB[nb]), g_wB + (size_t)(t+1)*64*KP, B_BYTES, mN);
            bulk_g2s(sptr(sBias[nb]), outb + (t+1)*64, 256, mN);
        }
        mbar_wait(sptr(&mbar[1 + buf]), (t >> 1) & 1);

        float c[4][4][4];
        #pragma unroll
        for (int mb = 0; mb < 4; mb++)
            #pragma unroll
            for (int nb = 0; nb < 4; nb++)
                #pragma unroll
                for (int i = 0; i < 4; i++) c[mb][nb][i] = 0.f;

        const uint32_t bB = sptr(sB[buf]) + bOff;
        for (int kc = 0; kc < 19; kc++) {
            uint32_t a[4][4], bfr[2][4];
            #pragma unroll
            for (int mb = 0; mb < 4; mb++)
                ldmx4(a[mb], aBase + (uint32_t)(mb*(16*KP*2) + kc*32));
            #pragma unroll
            for (int pq = 0; pq < 2; pq++)
                ldmx4(bfr[pq], bB + (uint32_t)(pq*(16*KP*2) + kc*32));
            #pragma unroll
            for (int mb = 0; mb < 4; mb++) {
                #pragma unroll
                for (int nb = 0; nb < 4; nb++) {
                    const int pq = nb >> 1, o = nb & 1;
                    mma_bf16(c[mb][nb], a[mb], bfr[pq][o], bfr[pq][o + 2]);
                }
            }
        }

        float bv[8];
        #pragma unroll
        for (int nb = 0; nb < 4; nb++) {
            bv[nb*2]   = sBias[buf][colL + nb*8];
            bv[nb*2+1] = sBias[buf][colL + nb*8 + 1];
        }
        #pragma unroll
        for (int mb = 0; mb < 4; mb++) {
            #pragma unroll
            for (int hh = 0; hh < 2; hh++) {
                const int s = hh << 1;
                float v[8];
                #pragma unroll
                for (int nb = 0; nb < 4; nb++) {
                    v[nb*2]   = c[mb][nb][s]   + bv[nb*2];
                    v[nb*2+1] = c[mb][nb][s+1] + bv[nb*2+1];
                }
                float lm = v[0];
                #pragma unroll
                for (int i = 1; i < 8; i++) lm = fmaxf(lm, v[i]);
                const int r = mb*2 + hh;
                float M = fmaxf(mrow[r], lm);
                float acc = srow[r] * __expf(mrow[r] - M);
                #pragma unroll
                for (int i = 0; i < 8; i++) acc += __expf(v[i] - M);
                srow[r] = acc;
                mrow[r] = M;
            }
        }
        __syncthreads();
    }

    #pragma unroll
    for (int r = 0; r < 8; r++) {
        float M = mrow[r], S = srow[r];
        #pragma unroll
        for (int d = 1; d <= 2; d <<= 1) {
            float M2 = __shfl_xor_sync(0xffffffffu, M, d);
            float S2 = __shfl_xor_sync(0xffffffffu, S, d);
            float Mn = fmaxf(M, M2);
            S = S * __expf(M - Mn) + S2 * __expf(M2 - Mn);
            M = Mn;
        }
        if ((lane & 3) == 0) {
            int row = wr*64 + (r >> 1)*16 + ((r & 1) << 3) + g;
            sMS[(wc*128 + row)*2]     = M;
            sMS[(wc*128 + row)*2 + 1] = S;
        }
    }
    __syncthreads();
    if (tid < 128) {
        float M0 = sMS[tid*2],         S0 = sMS[tid*2 + 1];
        float M1 = sMS[(128+tid)*2],   S1 = sMS[(128+tid)*2 + 1];
        float M = fmaxf(M0, M1);
        float S = S0 * __expf(M0 - M) + S1 * __expf(M1 - M);
        g_lse[blockIdx.x*128 + tid] = M + __logf(S);
    }
}

// ------------------------- final deterministic reduction -------------------------
__global__ void __launch_bounds__(256) sum_kernel(float* out)
{
    __shared__ float red[256];
    const int tid = threadIdx.x;
    float a = 0.f;
    for (int i = tid; i < NROWS; i += 256) a += g_lse[i] - g_tl[i];
    red[tid] = a;
    __syncthreads();
    for (int s = 128; s; s >>= 1) {
        if (tid < s) red[tid] += red[tid + s];
        __syncthreads();
    }
    if (tid == 0) out[0] = red[0] * (1.f / 256.f);
}

// ------------------------- host launcher -------------------------
extern "C" void kernel_launch(void* const* d_in, const int* in_sizes, int n_in,
                              void* d_out, int out_size)
{
    const int*   x       = (const int*)d_in[0];
    const int*   y       = (const int*)d_in[1];
    const float* enc_emb = (const float*)d_in[2];
    const float* encW    = (const float*)d_in[3];
    const float* encb    = (const float*)d_in[4];
    const float* dec_emb = (const float*)d_in[5];
    const float* decW    = (const float*)d_in[6];
    const float* decb    = (const float*)d_in[7];
    const float* outW    = (const float*)d_in[8];
    const float* outb    = (const float*)d_in[9];

    float* wtE; cudaGetSymbolAddress((void**)&wtE, g_WtE);
    float* wtD; cudaGetSymbolAddress((void**)&wtD, g_WtD);

    init_kernel<<<256, 256>>>();
    wconv_kernel<<<1024, 256>>>(outW);
    wtrans_kernel<<<256, 256>>>(encW, wtE);
    wtrans_kernel<<<256, 256>>>(decW, wtD);

    cudaFuncSetAttribute(rnn_cluster, cudaFuncAttributeMaxDynamicSharedMemorySize, CSMEM);
    rnn_cluster<<<128, RTHREADS, CSMEM>>>(enc_emb, x, encb, dec_emb, y, decb);

    tl_kernel<<<NROWS/8, 256>>>(y, outb);

    cudaFuncSetAttribute(gemm_lse_kernel, cudaFuncAttributeMaxDynamicSharedMemorySize, GSMEM);
    gemm_lse_kernel<<<254, 128, GSMEM>>>(outb);

    sum_kernel<<<1, 256>>>((float*)d_out);
}

// round 12
// speedup vs baseline: 1.0113x; 1.0113x over previous
#include <cuda_runtime.h>
#include <cuda_bf16.h>
#include <cstdint>
#include <cstddef>

#define H    300
#define B    256
#define NX   128
#define NY   128
#define VY   32000
#define NROWS 32512          /* 127*256 decoder logit rows */
#define NTILE_A 254          /* NROWS/128 */
#define KP   312             /* padded K stride in bf16 halves */

// ---- clustered recurrence geometry ----
#define GJ   320
#define GK2  304
#define JH   152
#define BSLC 4
#define RTHREADS 608
#define OFF_W    0
#define OFF_H    (GK2*JH*4)
#define OFF_RED  (OFF_H + 2*GK2*BSLC*4)
#define OFF_BIAS (OFF_RED + 4*JH*BSLC*4)
#define CSMEM    (OFF_BIAS + JH*4)

// ------------------------- scratch (device globals) -------------------------
__device__ __align__(16) __nv_bfloat16  g_hB[(size_t)NROWS*KP];   // decoder hidden rows (bf16)
__device__ __align__(16) __nv_bfloat16  g_wB[(size_t)VY*KP];      // outW in bf16, padded
__device__ __align__(16) float g_WtE[GK2*GJ];
__device__ __align__(16) float g_WtD[GK2*GJ];
__device__ float g_lse[NROWS];
__device__ float g_tl[NROWS];
__device__ int   g_ctr;

// ------------------------- PTX helpers -------------------------
__device__ __forceinline__ uint32_t sptr(const void* p) {
    return (uint32_t)__cvta_generic_to_shared(p);
}
__device__ __forceinline__ void mbar_init(uint32_t mbar, uint32_t cnt) {
    asm volatile("mbarrier.init.shared.b64 [%0], %1;" :: "r"(mbar), "r"(cnt) : "memory");
}
__device__ __forceinline__ void mbar_expect_tx(uint32_t mbar, uint32_t bytes) {
    asm volatile("mbarrier.arrive.expect_tx.shared.b64 _, [%0], %1;" :: "r"(mbar), "r"(bytes) : "memory");
}
__device__ __forceinline__ void mbar_wait(uint32_t mbar, uint32_t phase) {
    uint32_t done;
    do {
        asm volatile("{\n\t.reg .pred p;\n\t"
                     "mbarrier.try_wait.parity.shared::cta.b64 p, [%1], %2;\n\t"
                     "selp.b32 %0, 1, 0, p;\n\t}"
                     : "=r"(done) : "r"(mbar), "r"(phase) : "memory");
    } while (!done);
}
__device__ __forceinline__ void bulk_g2s(uint32_t dst, const void* src, uint32_t bytes, uint32_t mbar) {
    asm volatile("cp.async.bulk.shared::cluster.global.mbarrier::complete_tx::bytes [%0], [%1], %2, [%3];"
                 :: "r"(dst), "l"(src), "r"(bytes), "r"(mbar) : "memory");
}
__device__ __forceinline__ void ldmx4(uint32_t* r, uint32_t addr) {
    asm volatile("ldmatrix.sync.aligned.m8n8.x4.shared.b16 {%0,%1,%2,%3}, [%4];"
                 : "=r"(r[0]), "=r"(r[1]), "=r"(r[2]), "=r"(r[3]) : "r"(addr));
}
__device__ __forceinline__ void mma_bf16(float* c, const uint32_t* a, uint32_t b0, uint32_t b1) {
    asm volatile("mma.sync.aligned.m16n8k16.row.col.f32.bf16.bf16.f32 "
                 "{%0,%1,%2,%3},{%4,%5,%6,%7},{%8,%9},{%0,%1,%2,%3};"
                 : "+f"(c[0]), "+f"(c[1]), "+f"(c[2]), "+f"(c[3])
                 : "r"(a[0]), "r"(a[1]), "r"(a[2]), "r"(a[3]), "r"(b0), "r"(b1));
}
__device__ __forceinline__ uint32_t ctarank() {
    uint32_t r; asm("mov.u32 %0, %%cluster_ctarank;" : "=r"(r)); return r;
}
__device__ __forceinline__ void dsmem_st_f32(uint32_t addr, uint32_t rank, float v) {
    uint32_t pa;
    asm volatile("mapa.shared::cluster.u32 %0, %1, %2;" : "=r"(pa) : "r"(addr), "r"(rank));
    asm volatile("st.shared::cluster.f32 [%0], %1;" :: "r"(pa), "f"(v) : "memory");
}
__device__ __forceinline__ void cluster_sync() {
    asm volatile("barrier.cluster.arrive.aligned;" ::: "memory");
    asm volatile("barrier.cluster.wait.aligned;" ::: "memory");
}

// ------------------------- init: zero pad cols of g_hB + reset counter -------------------------
__global__ void init_kernel() {
    int stride = gridDim.x * blockDim.x;
    int i0 = blockIdx.x * blockDim.x + threadIdx.x;
    if (i0 == 0) g_ctr = 0;
    for (int i = i0; i < NROWS*3; i += stride) {
        int r = i / 3, c = i - r*3;
        *(uint32_t*)((char*)g_hB + (size_t)r*(KP*2) + 600 + c*4) = 0u;
    }
}

// ------------------------- outW fp32 -> bf16 padded -------------------------
__global__ void wconv_kernel(const float* __restrict__ outW) {
    int stride = gridDim.x * blockDim.x;
    for (int i = blockIdx.x * blockDim.x + threadIdx.x; i < VY*KP; i += stride) {
        int v = i / KP, k = i - v*KP;
        g_wB[i] = __float2bfloat16((k < H) ? outW[(size_t)v*H + k] : 0.f);
    }
}

// ------------------------- W -> transposed padded Wt[k][j] -------------------------
__global__ void wtrans_kernel(const float* __restrict__ W, float* __restrict__ Wt) {
    int stride = gridDim.x * blockDim.x;
    for (int i = blockIdx.x * blockDim.x + threadIdx.x; i < GK2*GJ; i += stride) {
        int k = i / GJ, j = i - k*GJ;
        Wt[i] = (j < H && k < H) ? W[j*H + k] : 0.f;
    }
}

// ------------------------- clustered persistent recurrence -------------------------
__global__ void __launch_bounds__(RTHREADS, 1) __cluster_dims__(2, 1, 1)
rnn_cluster(
    const float* __restrict__ enc_emb, const int* __restrict__ x, const float* __restrict__ encb,
    const float* __restrict__ dec_emb, const int* __restrict__ y, const float* __restrict__ decb)
{
    extern __shared__ __align__(16) char smraw[];
    float* sW    = (float*)(smraw + OFF_W);
    float* sH    = (float*)(smraw + OFF_H);
    float* sRed  = (float*)(smraw + OFF_RED);
    float* sBias = (float*)(smraw + OFF_BIAS);

    const int tid = threadIdx.x;
    const uint32_t rank = ctarank();
    const int j  = tid % JH;
    const int kq = tid / JH;
    const int b0 = (blockIdx.x >> 1) * BSLC;

    for (int i = tid; i < 2*GK2*BSLC; i += RTHREADS) sH[i] = 0.f;
    cluster_sync();

    int p = 0;
    for (int t = 0; t < NX + NY - 1; t++) {
        const bool enc = (t < NX);
        const float* emb = enc ? enc_emb : dec_emb;
        const int*   idx = enc ? (x + t*B) : (y + (t - NX)*B);

        if (t == 0 || t == NX) {
            const float* Wt   = enc ? g_WtE : g_WtD;
            const float* bsrc = enc ? encb : decb;
            for (int i = tid; i < GK2*(JH/4); i += RTHREADS) {
                int row = i / (JH/4), q = i - row*(JH/4);
                *(float4*)(sW + row*JH + q*4) =
                    *(const float4*)(Wt + row*GJ + rank*JH + q*4);
            }
            for (int i = tid; i < JH; i += RTHREADS) {
                int jg = rank*JH + i;
                sBias[i] = (jg < H) ? bsrc[jg] : 0.f;
            }
            __syncthreads();
        }

        const float* hcur = sH + p*(GK2*BSLC);
        float ax = 0.f, ay = 0.f, az = 0.f, aw = 0.f;
        const float* wp = sW + (kq*76)*JH + j;
        const float4* hp = (const float4*)(hcur) + kq*76;
        #pragma unroll 4
        for (int i = 0; i < 76; i++) {
            float w = wp[i*JH];
            float4 h = hp[i];
            ax += w*h.x; ay += w*h.y; az += w*h.z; aw += w*h.w;
        }
        ((float4*)sRed)[kq*JH + j] = make_float4(ax, ay, az, aw);
        __syncthreads();

        if (tid < JH) {
            const float4* r4 = (const float4*)sRed;
            float4 s0 = r4[tid], s1 = r4[JH + tid], s2 = r4[2*JH + tid], s3 = r4[3*JH + tid];
            float sv[4] = { s0.x+s1.x+s2.x+s3.x, s0.y+s1.y+s2.y+s3.y,
                            s0.z+s1.z+s2.z+s3.z, s0.w+s1.w+s2.w+s3.w };
            const int jg = rank*JH + tid;
            float* hn = sH + (p ^ 1)*(GK2*BSLC);
            const float bi = sBias[tid];
            #pragma unroll
            for (int b = 0; b < BSLC; b++) {
                float v = 0.f;
                if (jg < H) {
                    int ix = idx[b0 + b];
                    v = fmaxf(sv[b] + emb[(size_t)ix*H + jg] + bi, 0.f);
                }
                hn[jg*BSLC + b] = v;
                dsmem_st_f32(sptr(&hn[jg*BSLC + b]), rank ^ 1u, v);
                if (!enc && jg < H)
                    g_hB[(size_t)((t - NX)*B + b0 + b)*KP + jg] = __float2bfloat16(v);
            }
        }
        cluster_sync();
        p ^= 1;
    }
}

// ------------------------- target logit gather GEMV -------------------------
__global__ void __launch_bounds__(256) tl_kernel(const int* __restrict__ y,
                                                 const float* __restrict__ outb)
{
    int gw = blockIdx.x * 8 + (threadIdx.x >> 5);
    int lane = threadIdx.x & 31;
    if (gw >= NROWS) return;
    int t = gw >> 8, b = gw & 255;
    int tgt = y[(t+1)*B + b];
    const __nv_bfloat162* hr = (const __nv_bfloat162*)(g_hB + (size_t)gw*KP);
    const __nv_bfloat162* wr = (const __nv_bfloat162*)(g_wB + (size_t)tgt*KP);
    float acc = 0.f;
    for (int k = lane; k < KP/2; k += 32) {
        float2 hv = __bfloat1622float2(hr[k]);
        float2 wv = __bfloat1622float2(wr[k]);
        acc += hv.x*wv.x + hv.y*wv.y;
    }
    #pragma unroll
    for (int s = 16; s; s >>= 1) acc += __shfl_xor_sync(0xffffffffu, acc, s);
    if (lane == 0) g_tl[gw] = acc + __ldg(outb + tgt);
}

// ------------------------- persistent fused GEMM + online log-sum-exp -------------------------
// 148 persistent CTAs x 256 thr (8 warps as 4 row-groups x 2 col-groups).
// Each CTA claims A-tiles (128 rows) via atomic counter; sweeps 500 vocab tiles of 64.
#define OFF_A      0
#define OFF_B0     79872
#define OFF_B1     119808
#define OFF_BIAS0  159744
#define OFF_BIAS1  160000
#define OFF_MS     160256
#define OFF_MBAR   162304
#define OFF_SLOT   162368
#define GSMEM      162432
#define A_BYTES    79872u     /* 128*312*2 */
#define B_BYTES    39936u     /* 64*312*2 */

__global__ void __launch_bounds__(256, 1) gemm_lse_kernel(const float* __restrict__ outb)
{
    extern __shared__ __align__(1024) char smc[];
    __nv_bfloat16* sA = (__nv_bfloat16*)(smc + OFF_A);
    __nv_bfloat16* sB[2] = { (__nv_bfloat16*)(smc + OFF_B0), (__nv_bfloat16*)(smc + OFF_B1) };
    float* sBias[2] = { (float*)(smc + OFF_BIAS0), (float*)(smc + OFF_BIAS1) };
    float2* sMS = (float2*)(smc + OFF_MS);
    uint64_t* mbar = (uint64_t*)(smc + OFF_MBAR);
    int* sSlot = (int*)(smc + OFF_SLOT);

    const int tid = threadIdx.x, lane = tid & 31, wid = tid >> 5;
    const int wr = wid >> 1, wc = wid & 1;
    const uint32_t mbA = sptr(&mbar[0]);
    const uint32_t mbB[2] = { sptr(&mbar[1]), sptr(&mbar[2]) };

    if (tid == 0) {
        mbar_init(mbA, 1);
        mbar_init(mbB[0], 1);
        mbar_init(mbB[1], 1);
    }
    __syncthreads();

    const uint32_t aBase = sptr(sA) + (uint32_t)(((wr*32 + (lane & 15))*KP + ((lane >> 4) << 3)) * 2);
    const uint32_t bOff  = (uint32_t)(((wc*32 + (lane & 15))*KP + ((lane >> 4) << 3)) * 2);
    const int colL = wc*32 + ((lane & 3) << 1);
    const int g = lane >> 2;

    uint32_t cntA = 0, cntB0 = 0, cntB1 = 0;

    for (;;) {
        if (tid == 0) *sSlot = atomicAdd(&g_ctr, 1);
        __syncthreads();
        const int at = *sSlot;
        if (at >= NTILE_A) break;

        if (tid == 0) {
            mbar_expect_tx(mbA, A_BYTES);
            bulk_g2s(sptr(sA), g_hB + (size_t)at * 128 * KP, A_BYTES, mbA);
            mbar_expect_tx(mbB[0], B_BYTES + 256);
            bulk_g2s(sptr(sB[0]), g_wB, B_BYTES, mbB[0]);
            bulk_g2s(sptr(sBias[0]), outb, 256, mbB[0]);
        }

        float mrow[4], srow[4];
        #pragma unroll
        for (int i = 0; i < 4; i++) { mrow[i] = -1e30f; srow[i] = 0.f; }

        mbar_wait(mbA, cntA & 1); cntA++;

        for (int t = 0; t < 500; t++) {
            const int buf = t & 1;
            if (tid == 0 && t + 1 < 500) {
                const int nb = buf ^ 1;
                mbar_expect_tx(mbB[nb], B_BYTES + 256);
                bulk_g2s(sptr(sB[nb]), g_wB + (size_t)(t+1)*64*KP, B_BYTES, mbB[nb]);
                bulk_g2s(sptr(sBias[nb]), outb + (t+1)*64, 256, mbB[nb]);
            }
            if (buf == 0) { mbar_wait(mbB[0], cntB0 & 1); cntB0++; }
            else          { mbar_wait(mbB[1], cntB1 & 1); cntB1++; }

            float c[2][4][4];
            #pragma unroll
            for (int mb = 0; mb < 2; mb++)
                #pragma unroll
                for (int nb = 0; nb < 4; nb++)
                    #pragma unroll
                    for (int i = 0; i < 4; i++) c[mb][nb][i] = 0.f;

            const uint32_t bB = sptr(sB[buf]) + bOff;
            #pragma unroll 1
            for (int kc = 0; kc < 19; kc++) {
                uint32_t a[2][4], bfr[2][4];
                #pragma unroll
                for (int mb = 0; mb < 2; mb++)
                    ldmx4(a[mb], aBase + (uint32_t)(mb*(16*KP*2) + kc*32));
                #pragma unroll
                for (int pq = 0; pq < 2; pq++)
                    ldmx4(bfr[pq], bB + (uint32_t)(pq*(16*KP*2) + kc*32));
                #pragma unroll
                for (int mb = 0; mb < 2; mb++) {
                    #pragma unroll
                    for (int nb = 0; nb < 4; nb++) {
                        const int pq = nb >> 1, o = nb & 1;
                        mma_bf16(c[mb][nb], a[mb], bfr[pq][o], bfr[pq][o + 2]);
                    }
                }
            }

            float bv[8];
            #pragma unroll
            for (int nb = 0; nb < 4; nb++) {
                bv[nb*2]   = sBias[buf][colL + nb*8];
                bv[nb*2+1] = sBias[buf][colL + nb*8 + 1];
            }
            #pragma unroll
            for (int mb = 0; mb < 2; mb++) {
                #pragma unroll
                for (int hh = 0; hh < 2; hh++) {
                    const int s = hh << 1;
                    float v[8];
                    #pragma unroll
                    for (int nb = 0; nb < 4; nb++) {
                        v[nb*2]   = c[mb][nb][s]   + bv[nb*2];
                        v[nb*2+1] = c[mb][nb][s+1] + bv[nb*2+1];
                    }
                    float lm = v[0];
                    #pragma unroll
                    for (int i = 1; i < 8; i++) lm = fmaxf(lm, v[i]);
                    const int r = mb*2 + hh;
                    float M = fmaxf(mrow[r], lm);
                    float acc = srow[r] * __expf(mrow[r] - M);
                    #pragma unroll
                    for (int i = 0; i < 8; i++) acc += __expf(v[i] - M);
                    srow[r] = acc;
                    mrow[r] = M;
                }
            }
            __syncthreads();
        }

        // quad-reduce (cols within warp), stash, merge two col-halves
        #pragma unroll
        for (int r = 0; r < 4; r++) {
            float M = mrow[r], S = srow[r];
            #pragma unroll
            for (int d = 1; d <= 2; d <<= 1) {
                float M2 = __shfl_xor_sync(0xffffffffu, M, d);
                float S2 = __shfl_xor_sync(0xffffffffu, S, d);
                float Mn = fmaxf(M, M2);
                S = S * __expf(M - Mn) + S2 * __expf(M2 - Mn);
                M = Mn;
            }
            if ((lane & 3) == 0) {
                int row = wr*32 + (r >> 1)*16 + ((r & 1) << 3) + g;
                sMS[wc*128 + row] = make_float2(M, S);
            }
        }
        __syncthreads();
        if (tid < 128) {
            float2 a0 = sMS[tid], a1 = sMS[128 + tid];
            float M = fmaxf(a0.x, a1.x);
            float S = a0.y * __expf(a0.x - M) + a1.y * __expf(a1.x - M);
            g_lse[at*128 + tid] = M + __logf(S);
        }
        __syncthreads();
    }
}

// ------------------------- final deterministic reduction -------------------------
__global__ void __launch_bounds__(256) sum_kernel(float* out)
{
    __shared__ float red[256];
    const int tid = threadIdx.x;
    float a = 0.f;
    for (int i = tid; i < NROWS; i += 256) a += g_lse[i] - g_tl[i];
    red[tid] = a;
    __syncthreads();
    for (int s = 128; s; s >>= 1) {
        if (tid < s) red[tid] += red[tid + s];
        __syncthreads();
    }
    if (tid == 0) out[0] = red[0] * (1.f / 256.f);
}

// ------------------------- host launcher -------------------------
extern "C" void kernel_launch(void* const* d_in, const int* in_sizes, int n_in,
                              void* d_out, int out_size)
{
    const int*   x       = (const int*)d_in[0];
    const int*   y       = (const int*)d_in[1];
    const float* enc_emb = (const float*)d_in[2];
    const float* encW    = (const float*)d_in[3];
    const float* encb    = (const float*)d_in[4];
    const float* dec_emb = (const float*)d_in[5];
    const float* decW    = (const float*)d_in[6];
    const float* decb    = (const float*)d_in[7];
    const float* outW    = (const float*)d_in[8];
    const float* outb    = (const float*)d_in[9];

    float* wtE; cudaGetSymbolAddress((void**)&wtE, g_WtE);
    float* wtD; cudaGetSymbolAddress((void**)&wtD, g_WtD);

    init_kernel<<<256, 256>>>();
    wconv_kernel<<<1024, 256>>>(outW);
    wtrans_kernel<<<256, 256>>>(encW, wtE);
    wtrans_kernel<<<256, 256>>>(decW, wtD);

    cudaFuncSetAttribute(rnn_cluster, cudaFuncAttributeMaxDynamicSharedMemorySize, CSMEM);
    rnn_cluster<<<128, RTHREADS, CSMEM>>>(enc_emb, x, encb, dec_emb, y, decb);

    tl_kernel<<<NROWS/8, 256>>>(y, outb);

    cudaFuncSetAttribute(gemm_lse_kernel, cudaFuncAttributeMaxDynamicSharedMemorySize, GSMEM);
    gemm_lse_kernel<<<148, 256, GSMEM>>>(outb);

    sum_kernel<<<1, 256>>>((float*)d_out);
}